// round 16
// baseline (speedup 1.0000x reference)
#include <cuda_runtime.h>
#include <cuda_fp16.h>
#include <mma.h>
#include <math.h>

using namespace nvcuda;

#define B_BATCH 2048
#define DMODEL  768
#define M_ROWS  (B_BATCH * 64)   // 131072

__device__ __half g_Xh [(size_t)M_ROWS * DMODEL];
__device__ __half g_H  [(size_t)M_ROWS * DMODEL];
__device__ __half g_W1T [DMODEL * DMODEL];
__device__ __half g_WqkT[128 * DMODEL];

// ---------------- helpers ----------------
__device__ __forceinline__ unsigned s2u(const void* p) {
    unsigned a;
    asm("{ .reg .u64 t; cvta.to.shared.u64 t, %1; cvt.u32.u64 %0, t; }" : "=r"(a) : "l"(p));
    return a;
}
__device__ __forceinline__ void cp16(unsigned dst, const void* src) {
    asm volatile("cp.async.cg.shared.global [%0], [%1], 16;" :: "r"(dst), "l"(src));
}
#define CP_COMMIT() asm volatile("cp.async.commit_group;" ::: "memory")
#define CP_WAIT0()  asm volatile("cp.async.wait_group 0;" ::: "memory")

__device__ __forceinline__ unsigned h2u(__half2 v) { return *reinterpret_cast<unsigned*>(&v); }

// mish(x) = x*tanh(softplus(x)) = x*(t^2+2t)/(t^2+2t+2), t=e^x
__device__ __forceinline__ float mish_f(float x) {
    if (x > 40.0f) return x;
    float t = __expf(x);
    float u = t * t + 2.0f * t;
    return x * (u / (u + 2.0f));
}

// ---- geometry (R13-proven): CTA 128x128, K-chunk 32, warp tile 32x64 ----
#define KC        32
#define NCHUNK    (DMODEL / KC)      // 24
#define TS        40                 // tile row stride (elements)
#define TB        80                 // tile row stride (bytes)
#define TILE_SZ   10240              // 128 rows x 80B
#define OFF_A     0
#define OFF_B     TILE_SZ
#define BUF_SZ    (2 * TILE_SZ)      // 20480
#define BUF0_OFF  512
#define EPI_LD    132
#define SMEM_A    (512 + 128 * EPI_LD * 4)          // 68096
#define SMEM_B    (SMEM_A + 64 * 64 * 4 + 128)      // 84608

// ---------------------------------------------------------------------------
// X convert: fp32 -> fp16 one pass
// ---------------------------------------------------------------------------
__global__ __launch_bounds__(256) void k_xsplit(const float* __restrict__ X)
{
    const size_t total = (size_t)M_ROWS * DMODEL;
    size_t i = ((size_t)blockIdx.x * blockDim.x + threadIdx.x) * 8;
    const size_t stride = (size_t)gridDim.x * blockDim.x * 8;
    for (; i < total; i += stride) {
        float4 a = *(const float4*)(X + i);
        float4 b = *(const float4*)(X + i + 4);
        unsigned w0 = h2u(__floats2half2_rn(a.x, a.y));
        unsigned w1 = h2u(__floats2half2_rn(a.z, a.w));
        unsigned w2 = h2u(__floats2half2_rn(b.x, b.y));
        unsigned w3 = h2u(__floats2half2_rn(b.z, b.w));
        *(uint4*)(g_Xh + i) = make_uint4(w0, w1, w2, w3);
    }
}

// ---------------------------------------------------------------------------
// Weight transpose to fp16, all 3 weights in one launch. grid (28, 24).
// ---------------------------------------------------------------------------
__global__ void k_wconv(const float* __restrict__ W1, const float* __restrict__ Wq,
                        const float* __restrict__ Wk)
{
    __shared__ float tile[32][33];
    int bx = blockIdx.x;
    const float* src;
    __half* dst;
    int N;
    if (bx < 24)      { src = W1; dst = g_W1T;                N = 768; }
    else if (bx < 26) { src = Wq; dst = g_WqkT;               N = 64;  bx -= 24; }
    else              { src = Wk; dst = g_WqkT + 64 * DMODEL; N = 64;  bx -= 26; }
    int n0 = bx * 32, k0 = blockIdx.y * 32;
    int tx = threadIdx.x, ty = threadIdx.y;
#pragma unroll
    for (int i = 0; i < 32; i += 8)
        tile[ty + i][tx] = src[(size_t)(k0 + ty + i) * N + n0 + tx];
    __syncthreads();
#pragma unroll
    for (int i = 0; i < 32; i += 8) {
        int n = n0 + ty + i, k = k0 + tx;
        dst[(size_t)n * DMODEL + k] = __float2half_rn(tile[tx][ty + i]);
    }
}

// ---- fragments ----
typedef wmma::fragment<wmma::matrix_a, 16, 16, 16, __half, wmma::row_major> FragA;
typedef wmma::fragment<wmma::matrix_b, 16, 16, 16, __half, wmma::col_major> FragB;
typedef wmma::fragment<wmma::accumulator, 16, 16, 16, float> FragC;

// 32x64 warp tile, single-pass fp16 (R13 plain version — R15's pipelined
// variant measured neutral-negative, reverted)
__device__ __forceinline__ void compute_chunk(const char* buf, int wm, int wn,
                                              FragC c[2][4])
{
    const __half* As = (const __half*)(buf + OFF_A);
    const __half* Bs = (const __half*)(buf + OFF_B);
#pragma unroll
    for (int ks = 0; ks < 2; ks++) {
        FragA a[2];
#pragma unroll
        for (int i = 0; i < 2; i++)
            wmma::load_matrix_sync(a[i], As + (wm * 32 + i * 16) * TS + ks * 16, TS);
#pragma unroll
        for (int j = 0; j < 4; j++) {
            FragB b;
            wmma::load_matrix_sync(b, Bs + (wn * 64 + j * 16) * TS + ks * 16, TS);
            wmma::mma_sync(c[0][j], a[0], b, c[0][j]);
            wmma::mma_sync(c[1][j], a[1], b, c[1][j]);
        }
    }
}

__device__ __forceinline__ void stage_row32(unsigned dst, const __half* __restrict__ s)
{
    cp16(dst, s);
    cp16(dst + 16, s + 8);
}

// ---------------------------------------------------------------------------
// Kernel A: H = mish(Xh @ W1 + b1) -> g_H (fp16). grid (6,1024), 256 thr.
// __launch_bounds__(256, 3): cap regs ~85 -> 3 CTAs/SM (24 warps) to push
// the saturated L1 pipe and cover barrier bubbles.
// ---------------------------------------------------------------------------
__global__ __launch_bounds__(256, 3) void k_gemmA(const float* __restrict__ b1)
{
    extern __shared__ char smem[];
    const unsigned sb = s2u(smem);
    float* bias = (float*)smem;
    const int tid = threadIdx.x, wid = tid >> 5;
    const int wm = wid & 3, wn = wid >> 2;
    const int n0 = blockIdx.x * 128, m0 = blockIdx.y * 128;
    const int r = tid >> 1, half = tid & 1;

    if (tid < 128) bias[tid] = b1[n0 + tid];

    FragC c[2][4];
#pragma unroll
    for (int i = 0; i < 2; i++)
#pragma unroll
        for (int j = 0; j < 4; j++) wmma::fill_fragment(c[i][j], 0.0f);

    const __half* ar = g_Xh + (size_t)(m0 + r) * DMODEL + half * 16;
    const __half* wr = g_W1T + (size_t)(n0 + r) * DMODEL + half * 16;
    const unsigned arow = r * TB + half * 32;

    stage_row32(sb + BUF0_OFF + OFF_A + arow, ar);
    stage_row32(sb + BUF0_OFF + OFF_B + arow, wr);
    CP_COMMIT();
    CP_WAIT0();
    __syncthreads();

    for (int ch = 0; ch < NCHUNK; ch++) {
        const int cur = ch & 1;
        char* curbuf = smem + BUF0_OFF + cur * BUF_SZ;
        const unsigned nxtu = sb + BUF0_OFF + (1 - cur) * BUF_SZ;

        if (ch < NCHUNK - 1) {
            const int k0 = (ch + 1) * KC;
            stage_row32(nxtu + OFF_A + arow, ar + k0);
            stage_row32(nxtu + OFF_B + arow, wr + k0);
            CP_COMMIT();
        }
        compute_chunk(curbuf, wm, wn, c);
        if (ch < NCHUNK - 1) CP_WAIT0();
        __syncthreads();
    }

    // epilogue: dump accumulators, bias + mish, store fp16
    float* Cs = (float*)(smem + BUF0_OFF);
#pragma unroll
    for (int i = 0; i < 2; i++)
#pragma unroll
        for (int j = 0; j < 4; j++)
            wmma::store_matrix_sync(Cs + (wm * 32 + i * 16) * EPI_LD + wn * 64 + j * 16,
                                    c[i][j], EPI_LD, wmma::mem_row_major);
    __syncthreads();

    const float* crow = Cs + r * EPI_LD + half * 64;
    const float* bptr = bias + half * 64;
    __half* dh = g_H + (size_t)(m0 + r) * DMODEL + n0 + half * 64;
#pragma unroll
    for (int blk = 0; blk < 8; blk++) {
        unsigned hw[4];
#pragma unroll
        for (int e = 0; e < 4; e++) {
            float v0 = mish_f(crow[blk * 8 + 2 * e]     + bptr[blk * 8 + 2 * e]);
            float v1 = mish_f(crow[blk * 8 + 2 * e + 1] + bptr[blk * 8 + 2 * e + 1]);
            hw[e] = h2u(__floats2half2_rn(v0, v1));
        }
        *(uint4*)(dh + blk * 8) = make_uint4(hw[0], hw[1], hw[2], hw[3]);
    }
}

// ---------------------------------------------------------------------------
// Kernel BC (fused, R13-proven): QK = H @ [Wq|Wk] + bias, then scores +
// promotion + gather for the CTA's 2 batches. grid 1024, 256 thr, 2 CTAs/SM.
// ---------------------------------------------------------------------------
__global__ __launch_bounds__(256, 2) void k_gemmBC(
    const float* __restrict__ bq, const float* __restrict__ bk,
    const float* __restrict__ Wp, const float* __restrict__ bp,
    const int* __restrict__ indices, float* __restrict__ out)
{
    extern __shared__ char smem[];
    const unsigned sb = s2u(smem);
    float* bias = (float*)smem;
    const int tid = threadIdx.x, wid = tid >> 5;
    const int wm = wid & 3, wn = wid >> 2;
    const int m0 = blockIdx.x * 128;
    const int r = tid >> 1, half = tid & 1;

    if (tid < 128) bias[tid] = (tid < 64) ? bq[tid] : bk[tid - 64];

    FragC c[2][4];
#pragma unroll
    for (int i = 0; i < 2; i++)
#pragma unroll
        for (int j = 0; j < 4; j++) wmma::fill_fragment(c[i][j], 0.0f);

    const __half* ahr = g_H + (size_t)(m0 + r) * DMODEL + half * 16;
    const __half* wr  = g_WqkT + (size_t)r * DMODEL + half * 16;
    const unsigned arow = r * TB + half * 32;

    stage_row32(sb + BUF0_OFF + OFF_A + arow, ahr);
    stage_row32(sb + BUF0_OFF + OFF_B + arow, wr);
    CP_COMMIT();
    CP_WAIT0();
    __syncthreads();

    for (int ch = 0; ch < NCHUNK; ch++) {
        const int cur = ch & 1;
        char* curbuf = smem + BUF0_OFF + cur * BUF_SZ;
        const unsigned nxtu = sb + BUF0_OFF + (1 - cur) * BUF_SZ;

        if (ch < NCHUNK - 1) {
            const int k0 = (ch + 1) * KC;
            stage_row32(nxtu + OFF_A + arow, ahr + k0);
            stage_row32(nxtu + OFF_B + arow, wr + k0);
            CP_COMMIT();
        }
        compute_chunk(curbuf, wm, wn, c);
        if (ch < NCHUNK - 1) CP_WAIT0();
        __syncthreads();
    }

    // dump QK + bias into Cs: row = m-row, col 0..63 = q, 64..127 = k
    float* Cs = (float*)(smem + BUF0_OFF);
#pragma unroll
    for (int i = 0; i < 2; i++)
#pragma unroll
        for (int j = 0; j < 4; j++)
            wmma::store_matrix_sync(Cs + (wm * 32 + i * 16) * EPI_LD + wn * 64 + j * 16,
                                    c[i][j], EPI_LD, wmma::mem_row_major);
    __syncthreads();
    {
        float* crow = Cs + r * EPI_LD + half * 64;
        const float* bptr = bias + half * 64;
#pragma unroll
        for (int e = 0; e < 16; e++) {
            float4 v = *(float4*)(crow + e * 4);
            v.x += bptr[e * 4 + 0]; v.y += bptr[e * 4 + 1];
            v.z += bptr[e * 4 + 2]; v.w += bptr[e * 4 + 3];
            *(float4*)(crow + e * 4) = v;
        }
    }
    __syncthreads();

    float* s_s   = (float*)(smem + SMEM_A);
    float* prom2 = s_s + 64 * 64;
    const int tx = tid & 15, ty = tid >> 4;
    const int i0 = ty * 4, j0 = tx * 4;

    for (int bb = 0; bb < 2; bb++) {
        const float* qs = Cs + bb * 64 * EPI_LD;
        const float* ks = Cs + bb * 64 * EPI_LD + 64;

        float acc[4][4] = {};
#pragma unroll 16
        for (int d = 0; d < 64; d++) {
            float qv[4], kv[4];
#pragma unroll
            for (int a = 0; a < 4; a++) { qv[a] = qs[(i0 + a) * EPI_LD + d]; kv[a] = ks[(j0 + a) * EPI_LD + d]; }
#pragma unroll
            for (int a = 0; a < 4; a++)
#pragma unroll
                for (int e = 0; e < 4; e++) acc[a][e] += qv[a] * kv[e];
        }
#pragma unroll
        for (int a = 0; a < 4; a++)
#pragma unroll
            for (int e = 0; e < 4; e++) s_s[(i0 + a) * 64 + j0 + e] = acc[a][e] * 0.125f;

        if (tid < 24) {
            int jr = 56 + tid / 3, cc = tid % 3;
            float pa = bp[cc] + bp[3];
#pragma unroll
            for (int d = 0; d < 64; d++)
                pa += ks[jr * EPI_LD + d] * (Wp[d * 4 + cc] + Wp[d * 4 + 3]);
            prom2[tid] = pa;
        }
        __syncthreads();

        float* orow = out + (size_t)(blockIdx.x * 2 + bb) * 1858;
        for (int t = tid; t < 1858; t += 256) {
            int id = indices[t];
            float v;
            if (id < 4096) v = s_s[(id >> 6) * 64 + (id & 63)];
            else {
                int p = id - 4096, i = p / 3;
                v = s_s[(48 + (i >> 3)) * 64 + 56 + (i & 7)] + prom2[p % 24];
            }
            orow[t] = v;
        }
        __syncthreads();
    }
}

// ---------------------------------------------------------------------------
extern "C" void kernel_launch(void* const* d_in, const int* in_sizes, int n_in,
                              void* d_out, int out_size)
{
    const float* x  = (const float*)d_in[0];
    const float* W1 = (const float*)d_in[1];
    const float* b1 = (const float*)d_in[2];
    const float* Wq = (const float*)d_in[3];
    const float* bq = (const float*)d_in[4];
    const float* Wk = (const float*)d_in[5];
    const float* bk = (const float*)d_in[6];
    const float* Wp = (const float*)d_in[7];
    const float* bp = (const float*)d_in[8];
    const int*  idx = (const int*)d_in[9];

    cudaFuncSetAttribute(k_gemmA,  cudaFuncAttributeMaxDynamicSharedMemorySize, SMEM_A);
    cudaFuncSetAttribute(k_gemmBC, cudaFuncAttributeMaxDynamicSharedMemorySize, SMEM_B);

    k_xsplit<<<4736, 256>>>(x);
    k_wconv<<<dim3(28, 24), dim3(32, 8)>>>(W1, Wq, Wk);

    k_gemmA<<<dim3(6, 1024), 256, SMEM_A>>>(b1);
    k_gemmBC<<<1024, 256, SMEM_B>>>(bq, bk, Wp, bp, idx, (float*)d_out);
}

// round 17
// speedup vs baseline: 1.4576x; 1.4576x over previous
#include <cuda_runtime.h>
#include <cuda_fp16.h>
#include <mma.h>
#include <math.h>

using namespace nvcuda;

#define B_BATCH 2048
#define DMODEL  768
#define M_ROWS  (B_BATCH * 64)   // 131072

__device__ __half g_Xh [(size_t)M_ROWS * DMODEL];
__device__ __half g_H  [(size_t)M_ROWS * DMODEL];
__device__ __half g_W1T [DMODEL * DMODEL];
__device__ __half g_WqkT[128 * DMODEL];

// ---------------- helpers ----------------
__device__ __forceinline__ unsigned s2u(const void* p) {
    unsigned a;
    asm("{ .reg .u64 t; cvta.to.shared.u64 t, %1; cvt.u32.u64 %0, t; }" : "=r"(a) : "l"(p));
    return a;
}
__device__ __forceinline__ void cp16(unsigned dst, const void* src) {
    asm volatile("cp.async.cg.shared.global [%0], [%1], 16;" :: "r"(dst), "l"(src));
}
#define CP_COMMIT() asm volatile("cp.async.commit_group;" ::: "memory")
#define CP_WAIT0()  asm volatile("cp.async.wait_group 0;" ::: "memory")

__device__ __forceinline__ unsigned h2u(__half2 v) { return *reinterpret_cast<unsigned*>(&v); }

// mish(x) = x*tanh(softplus(x)) = x*(t^2+2t)/(t^2+2t+2), t=e^x
__device__ __forceinline__ float mish_f(float x) {
    if (x > 40.0f) return x;
    float t = __expf(x);
    float u = t * t + 2.0f * t;
    return x * (u / (u + 2.0f));
}

// ---- geometry (R13-proven): CTA 128x128, K-chunk 32, warp tile 32x64 ----
#define KC        32
#define NCHUNK    (DMODEL / KC)      // 24
#define TS        40                 // tile row stride (elements)
#define TB        80                 // tile row stride (bytes)
#define TILE_SZ   10240              // 128 rows x 80B
#define OFF_A     0
#define OFF_B     TILE_SZ
#define BUF_SZ    (2 * TILE_SZ)      // 20480
#define BUF0_OFF  512
#define EPI_LD    132
#define SMEM_A    (512 + 128 * EPI_LD * 4)          // 68096
#define KT_LD     68                                 // kT row stride (floats)
#define OFF_SS    SMEM_A                             // scores 64*64*4 = 16384
#define OFF_PROM  (OFF_SS + 64 * 64 * 4)             // 96 B used
#define OFF_KT    (OFF_PROM + 128)                   // 64*68*4 = 17408
#define SMEM_B    (OFF_KT + 64 * KT_LD * 4)          // 102016

// ---------------------------------------------------------------------------
// X convert: fp32 -> fp16 one pass
// ---------------------------------------------------------------------------
__global__ __launch_bounds__(256) void k_xsplit(const float* __restrict__ X)
{
    const size_t total = (size_t)M_ROWS * DMODEL;
    size_t i = ((size_t)blockIdx.x * blockDim.x + threadIdx.x) * 8;
    const size_t stride = (size_t)gridDim.x * blockDim.x * 8;
    for (; i < total; i += stride) {
        float4 a = *(const float4*)(X + i);
        float4 b = *(const float4*)(X + i + 4);
        unsigned w0 = h2u(__floats2half2_rn(a.x, a.y));
        unsigned w1 = h2u(__floats2half2_rn(a.z, a.w));
        unsigned w2 = h2u(__floats2half2_rn(b.x, b.y));
        unsigned w3 = h2u(__floats2half2_rn(b.z, b.w));
        *(uint4*)(g_Xh + i) = make_uint4(w0, w1, w2, w3);
    }
}

// ---------------------------------------------------------------------------
// Weight transpose to fp16, all 3 weights in one launch. grid (28, 24).
// ---------------------------------------------------------------------------
__global__ void k_wconv(const float* __restrict__ W1, const float* __restrict__ Wq,
                        const float* __restrict__ Wk)
{
    __shared__ float tile[32][33];
    int bx = blockIdx.x;
    const float* src;
    __half* dst;
    int N;
    if (bx < 24)      { src = W1; dst = g_W1T;                N = 768; }
    else if (bx < 26) { src = Wq; dst = g_WqkT;               N = 64;  bx -= 24; }
    else              { src = Wk; dst = g_WqkT + 64 * DMODEL; N = 64;  bx -= 26; }
    int n0 = bx * 32, k0 = blockIdx.y * 32;
    int tx = threadIdx.x, ty = threadIdx.y;
#pragma unroll
    for (int i = 0; i < 32; i += 8)
        tile[ty + i][tx] = src[(size_t)(k0 + ty + i) * N + n0 + tx];
    __syncthreads();
#pragma unroll
    for (int i = 0; i < 32; i += 8) {
        int n = n0 + ty + i, k = k0 + tx;
        dst[(size_t)n * DMODEL + k] = __float2half_rn(tile[tx][ty + i]);
    }
}

// ---- fragments ----
typedef wmma::fragment<wmma::matrix_a, 16, 16, 16, __half, wmma::row_major> FragA;
typedef wmma::fragment<wmma::matrix_b, 16, 16, 16, __half, wmma::col_major> FragB;
typedef wmma::fragment<wmma::accumulator, 16, 16, 16, float> FragC;

// 32x64 warp tile, single-pass fp16 (R13 plain version)
__device__ __forceinline__ void compute_chunk(const char* buf, int wm, int wn,
                                              FragC c[2][4])
{
    const __half* As = (const __half*)(buf + OFF_A);
    const __half* Bs = (const __half*)(buf + OFF_B);
#pragma unroll
    for (int ks = 0; ks < 2; ks++) {
        FragA a[2];
#pragma unroll
        for (int i = 0; i < 2; i++)
            wmma::load_matrix_sync(a[i], As + (wm * 32 + i * 16) * TS + ks * 16, TS);
#pragma unroll
        for (int j = 0; j < 4; j++) {
            FragB b;
            wmma::load_matrix_sync(b, Bs + (wn * 64 + j * 16) * TS + ks * 16, TS);
            wmma::mma_sync(c[0][j], a[0], b, c[0][j]);
            wmma::mma_sync(c[1][j], a[1], b, c[1][j]);
        }
    }
}

__device__ __forceinline__ void stage_row32(unsigned dst, const __half* __restrict__ s)
{
    cp16(dst, s);
    cp16(dst + 16, s + 8);
}

// ---------------------------------------------------------------------------
// Kernel A: H = mish(Xh @ W1 + b1) -> g_H (fp16). grid (6,1024), 256 thr,
// 2 CTAs/SM (R16's occ=3 spilled and regressed; reverted).
// ---------------------------------------------------------------------------
__global__ __launch_bounds__(256, 2) void k_gemmA(const float* __restrict__ b1)
{
    extern __shared__ char smem[];
    const unsigned sb = s2u(smem);
    float* bias = (float*)smem;
    const int tid = threadIdx.x, wid = tid >> 5;
    const int wm = wid & 3, wn = wid >> 2;
    const int n0 = blockIdx.x * 128, m0 = blockIdx.y * 128;
    const int r = tid >> 1, half = tid & 1;

    if (tid < 128) bias[tid] = b1[n0 + tid];

    FragC c[2][4];
#pragma unroll
    for (int i = 0; i < 2; i++)
#pragma unroll
        for (int j = 0; j < 4; j++) wmma::fill_fragment(c[i][j], 0.0f);

    const __half* ar = g_Xh + (size_t)(m0 + r) * DMODEL + half * 16;
    const __half* wr = g_W1T + (size_t)(n0 + r) * DMODEL + half * 16;
    const unsigned arow = r * TB + half * 32;

    stage_row32(sb + BUF0_OFF + OFF_A + arow, ar);
    stage_row32(sb + BUF0_OFF + OFF_B + arow, wr);
    CP_COMMIT();
    CP_WAIT0();
    __syncthreads();

    for (int ch = 0; ch < NCHUNK; ch++) {
        const int cur = ch & 1;
        char* curbuf = smem + BUF0_OFF + cur * BUF_SZ;
        const unsigned nxtu = sb + BUF0_OFF + (1 - cur) * BUF_SZ;

        if (ch < NCHUNK - 1) {
            const int k0 = (ch + 1) * KC;
            stage_row32(nxtu + OFF_A + arow, ar + k0);
            stage_row32(nxtu + OFF_B + arow, wr + k0);
            CP_COMMIT();
        }
        compute_chunk(curbuf, wm, wn, c);
        if (ch < NCHUNK - 1) CP_WAIT0();
        __syncthreads();
    }

    // epilogue: dump accumulators, bias + mish, store fp16
    float* Cs = (float*)(smem + BUF0_OFF);
#pragma unroll
    for (int i = 0; i < 2; i++)
#pragma unroll
        for (int j = 0; j < 4; j++)
            wmma::store_matrix_sync(Cs + (wm * 32 + i * 16) * EPI_LD + wn * 64 + j * 16,
                                    c[i][j], EPI_LD, wmma::mem_row_major);
    __syncthreads();

    const float* crow = Cs + r * EPI_LD + half * 64;
    const float* bptr = bias + half * 64;
    __half* dh = g_H + (size_t)(m0 + r) * DMODEL + n0 + half * 64;
#pragma unroll
    for (int blk = 0; blk < 8; blk++) {
        unsigned hw[4];
#pragma unroll
        for (int e = 0; e < 4; e++) {
            float v0 = mish_f(crow[blk * 8 + 2 * e]     + bptr[blk * 8 + 2 * e]);
            float v1 = mish_f(crow[blk * 8 + 2 * e + 1] + bptr[blk * 8 + 2 * e + 1]);
            hw[e] = h2u(__floats2half2_rn(v0, v1));
        }
        *(uint4*)(dh + blk * 8) = make_uint4(hw[0], hw[1], hw[2], hw[3]);
    }
}

// ---------------------------------------------------------------------------
// Kernel BC (fused): QK = H @ [Wq|Wk] + bias, then scores + promotion +
// gather. Scores now read k via a bank-clean transposed tile (kT, LDS.128)
// instead of 8-way-conflicted strided loads from Cs. grid 1024, 256 thr.
// ---------------------------------------------------------------------------
__global__ __launch_bounds__(256, 2) void k_gemmBC(
    const float* __restrict__ bq, const float* __restrict__ bk,
    const float* __restrict__ Wp, const float* __restrict__ bp,
    const int* __restrict__ indices, float* __restrict__ out)
{
    extern __shared__ char smem[];
    const unsigned sb = s2u(smem);
    float* bias = (float*)smem;
    const int tid = threadIdx.x, wid = tid >> 5;
    const int wm = wid & 3, wn = wid >> 2;
    const int m0 = blockIdx.x * 128;
    const int r = tid >> 1, half = tid & 1;

    if (tid < 128) bias[tid] = (tid < 64) ? bq[tid] : bk[tid - 64];

    FragC c[2][4];
#pragma unroll
    for (int i = 0; i < 2; i++)
#pragma unroll
        for (int j = 0; j < 4; j++) wmma::fill_fragment(c[i][j], 0.0f);

    const __half* ahr = g_H + (size_t)(m0 + r) * DMODEL + half * 16;
    const __half* wr  = g_WqkT + (size_t)r * DMODEL + half * 16;
    const unsigned arow = r * TB + half * 32;

    stage_row32(sb + BUF0_OFF + OFF_A + arow, ahr);
    stage_row32(sb + BUF0_OFF + OFF_B + arow, wr);
    CP_COMMIT();
    CP_WAIT0();
    __syncthreads();

    for (int ch = 0; ch < NCHUNK; ch++) {
        const int cur = ch & 1;
        char* curbuf = smem + BUF0_OFF + cur * BUF_SZ;
        const unsigned nxtu = sb + BUF0_OFF + (1 - cur) * BUF_SZ;

        if (ch < NCHUNK - 1) {
            const int k0 = (ch + 1) * KC;
            stage_row32(nxtu + OFF_A + arow, ahr + k0);
            stage_row32(nxtu + OFF_B + arow, wr + k0);
            CP_COMMIT();
        }
        compute_chunk(curbuf, wm, wn, c);
        if (ch < NCHUNK - 1) CP_WAIT0();
        __syncthreads();
    }

    // dump QK + bias into Cs: row = m-row, col 0..63 = q, 64..127 = k
    float* Cs = (float*)(smem + BUF0_OFF);
#pragma unroll
    for (int i = 0; i < 2; i++)
#pragma unroll
        for (int j = 0; j < 4; j++)
            wmma::store_matrix_sync(Cs + (wm * 32 + i * 16) * EPI_LD + wn * 64 + j * 16,
                                    c[i][j], EPI_LD, wmma::mem_row_major);
    __syncthreads();
    {
        float* crow = Cs + r * EPI_LD + half * 64;
        const float* bptr = bias + half * 64;
#pragma unroll
        for (int e = 0; e < 16; e++) {
            float4 v = *(float4*)(crow + e * 4);
            v.x += bptr[e * 4 + 0]; v.y += bptr[e * 4 + 1];
            v.z += bptr[e * 4 + 2]; v.w += bptr[e * 4 + 3];
            *(float4*)(crow + e * 4) = v;
        }
    }
    __syncthreads();

    float* s_s   = (float*)(smem + OFF_SS);
    float* prom2 = (float*)(smem + OFF_PROM);
    float* kT    = (float*)(smem + OFF_KT);     // [64 d][KT_LD], kT[d][j] = k[j][d]
    const int tx = tid & 15, ty = tid >> 4;
    const int i0 = ty * 4, j0 = tx * 4;

    for (int bb = 0; bb < 2; bb++) {
        const float* qs = Cs + bb * 64 * EPI_LD;
        const float* ks = Cs + bb * 64 * EPI_LD + 64;

        // transpose k into kT (conflict-light one-time pass)
        for (int idx = tid; idx < 4096; idx += 256) {
            int j = idx >> 6, d = idx & 63;
            kT[d * KT_LD + j] = ks[j * EPI_LD + d];
        }
        __syncthreads();

        float acc[4][4] = {};
#pragma unroll 16
        for (int d = 0; d < 64; d++) {
            float4 kv = *(const float4*)(kT + d * KT_LD + j0);   // LDS.128
            float qv[4];
#pragma unroll
            for (int a = 0; a < 4; a++) qv[a] = qs[(i0 + a) * EPI_LD + d];
#pragma unroll
            for (int a = 0; a < 4; a++) {
                acc[a][0] += qv[a] * kv.x;
                acc[a][1] += qv[a] * kv.y;
                acc[a][2] += qv[a] * kv.z;
                acc[a][3] += qv[a] * kv.w;
            }
        }
#pragma unroll
        for (int a = 0; a < 4; a++) {
            float4 o = make_float4(acc[a][0] * 0.125f, acc[a][1] * 0.125f,
                                   acc[a][2] * 0.125f, acc[a][3] * 0.125f);
            *(float4*)(s_s + (i0 + a) * 64 + j0) = o;
        }

        if (tid < 24) {
            int jr = 56 + tid / 3, cc = tid % 3;
            float pa = bp[cc] + bp[3];
#pragma unroll
            for (int d = 0; d < 64; d++)
                pa += kT[d * KT_LD + jr] * (Wp[d * 4 + cc] + Wp[d * 4 + 3]);
            prom2[tid] = pa;
        }
        __syncthreads();

        float* orow = out + (size_t)(blockIdx.x * 2 + bb) * 1858;
        for (int t = tid; t < 1858; t += 256) {
            int id = indices[t];
            float v;
            if (id < 4096) v = s_s[(id >> 6) * 64 + (id & 63)];
            else {
                int p = id - 4096, i = p / 3;
                v = s_s[(48 + (i >> 3)) * 64 + 56 + (i & 7)] + prom2[p % 24];
            }
            orow[t] = v;
        }
        __syncthreads();
    }
}

// ---------------------------------------------------------------------------
extern "C" void kernel_launch(void* const* d_in, const int* in_sizes, int n_in,
                              void* d_out, int out_size)
{
    const float* x  = (const float*)d_in[0];
    const float* W1 = (const float*)d_in[1];
    const float* b1 = (const float*)d_in[2];
    const float* Wq = (const float*)d_in[3];
    const float* bq = (const float*)d_in[4];
    const float* Wk = (const float*)d_in[5];
    const float* bk = (const float*)d_in[6];
    const float* Wp = (const float*)d_in[7];
    const float* bp = (const float*)d_in[8];
    const int*  idx = (const int*)d_in[9];

    cudaFuncSetAttribute(k_gemmA,  cudaFuncAttributeMaxDynamicSharedMemorySize, SMEM_A);
    cudaFuncSetAttribute(k_gemmBC, cudaFuncAttributeMaxDynamicSharedMemorySize, SMEM_B);

    k_xsplit<<<4736, 256>>>(x);
    k_wconv<<<dim3(28, 24), dim3(32, 8)>>>(W1, Wq, Wk);

    k_gemmA<<<dim3(6, 1024), 256, SMEM_A>>>(b1);
    k_gemmBC<<<1024, 256, SMEM_B>>>(bq, bk, Wp, bp, idx, (float*)d_out);
}